// round 12
// baseline (speedup 1.0000x reference)
#include <cuda_runtime.h>
#include <cuda_fp16.h>
#include <cstdint>
#include <math.h>

// ---------------- problem constants ----------------
#define B_    16
#define CIN   512
#define COUT  512
#define HH    64
#define WW    64
#define PIX   4096
#define SD    512
#define EPSV  1e-8f
#define MOD_SCALE_F  0.04419417382415922f   // 1/sqrt(512)
#define CONV_SCALE_F 0.014731391274719738f  // 1/sqrt(512*9)
#define CS2_F        0.00021701388888888888f

// ---------------- tiling ----------------
// CTA: M=128 couts x N=256 pixels (4 image rows), K-chunk=64 cins, 72 chunks
#define NCH   72
#define ROWB  144                // padded smem row bytes (128B data + 16B pad)
#define A_O   0
#define B_O   18432              // A: 128 rows * 144B
#define SSTAGE 55296             // A 18432 | B 36864 (256 rows * 144B)
#define NSTG  4
#define DSMEM (NSTG * SSTAGE)    // 221184 B

// ---------------- scratch ----------------
__device__ float g_s[B_ * CIN];
__device__ float g_wsq[COUT * CIN];
__device__ float g_demod[B_ * COUT];
__device__ __half g_xh[(size_t)B_ * PIX * CIN];   // [b][pixel][ci]  (x * s, fp16)
__device__ __half g_wh[(size_t)COUT * 9 * CIN];   // [cout][tap][ci] (fp16)

// ---------------- PTX helpers (baseline PTX, sm_80-class) ----------------
__device__ __forceinline__ uint32_t smem_u32(const void* p) {
    uint32_t a;
    asm("{ .reg .u64 t; cvta.to.shared.u64 t, %1; cvt.u32.u64 %0, t; }" : "=r"(a) : "l"(p));
    return a;
}
__device__ __forceinline__ void cpa16(uint32_t dst, const void* src, int srcsize) {
    asm volatile("cp.async.cg.shared.global [%0], [%1], 16, %2;\n"
                 :: "r"(dst), "l"(src), "r"(srcsize) : "memory");
}
#define CP_COMMIT() asm volatile("cp.async.commit_group;" ::: "memory")
#define CP_WAIT2()  asm volatile("cp.async.wait_group 2;" ::: "memory")
#define CP_WAIT1()  asm volatile("cp.async.wait_group 1;" ::: "memory")
#define CP_WAIT0()  asm volatile("cp.async.wait_group 0;" ::: "memory")

#define LDSM4(r, addr) \
    asm volatile("ldmatrix.sync.aligned.m8n8.x4.shared.b16 {%0,%1,%2,%3}, [%4];" \
        : "=r"((r)[0]), "=r"((r)[1]), "=r"((r)[2]), "=r"((r)[3]) : "r"(addr))

// fp16-accumulator MMA: D(f16x2 x2) = A*B + C(f16x2 x2)
#define MMA16816H(d0, d1, a, b0, b1, c0, c1) \
    asm volatile("mma.sync.aligned.m16n8k16.row.col.f16.f16.f16.f16 " \
        "{%0,%1},{%2,%3,%4,%5},{%6,%7},{%8,%9};" \
        : "=r"(d0), "=r"(d1) \
        : "r"((a)[0]), "r"((a)[1]), "r"((a)[2]), "r"((a)[3]), \
          "r"(b0), "r"(b1), "r"(c0), "r"(c1))

// ---------------- preprocessing kernels ----------------
__global__ void modulate_kernel(const float* __restrict__ style,
                                const float* __restrict__ mw,
                                const float* __restrict__ mb) {
    int warp = (blockIdx.x * blockDim.x + threadIdx.x) >> 5;
    int lane = threadIdx.x & 31;
    if (warp >= B_ * CIN) return;
    int b = warp / CIN, cin = warp % CIN;
    const float* srow = style + (size_t)b * SD;
    const float* wrow = mw + (size_t)cin * SD;
    float sum = 0.f;
    #pragma unroll 4
    for (int j = lane; j < SD; j += 32) sum += srow[j] * wrow[j];
    #pragma unroll
    for (int o = 16; o; o >>= 1) sum += __shfl_xor_sync(0xffffffffu, sum, o);
    if (lane == 0) g_s[warp] = sum * MOD_SCALE_F + mb[cin];
}

// weights: per (cout, cin) thread: read 9 taps, write fp16 [cout][tap][cin] + wsq
__global__ void wprep_kernel(const float* __restrict__ cw) {
    int idx = blockIdx.x * blockDim.x + threadIdx.x;
    if (idx >= COUT * CIN) return;
    int cout = idx / CIN;
    int ci = idx - cout * CIN;
    const float* p = cw + (size_t)idx * 9;
    float sq = 0.f;
    #pragma unroll
    for (int k = 0; k < 9; k++) {
        float v = p[k];
        sq += v * v;
        g_wh[((size_t)cout * 9 + k) * CIN + ci] = __float2half_rn(v);
    }
    g_wsq[idx] = sq;
}

__global__ void demod_kernel() {
    int warp = (blockIdx.x * blockDim.x + threadIdx.x) >> 5;
    int lane = threadIdx.x & 31;
    if (warp >= B_ * COUT) return;
    int b = warp / COUT, cout = warp % COUT;
    const float* srow = g_s + (size_t)b * CIN;
    const float* wrow = g_wsq + (size_t)cout * CIN;
    float sum = 0.f;
    #pragma unroll 4
    for (int cin = lane; cin < CIN; cin += 32) {
        float s = srow[cin];
        sum += s * s * wrow[cin];
    }
    #pragma unroll
    for (int o = 16; o; o >>= 1) sum += __shfl_xor_sync(0xffffffffu, sum, o);
    if (lane == 0) g_demod[warp] = rsqrtf(sum * CS2_F + EPSV);
}

// input: [b][ci][p] * s[b][ci] -> channel-last fp16 [b][p][ci]
__global__ __launch_bounds__(256) void xprep_kernel(const float* __restrict__ x) {
    __shared__ float tile[64][65];
    int b = blockIdx.z, ci0 = blockIdx.y * 64, p0 = blockIdx.x * 64;
    int tid = threadIdx.x;
    int j = tid & 63, i0 = tid >> 6;
    #pragma unroll
    for (int ii = 0; ii < 16; ii++) {
        int ci = i0 + ii * 4;
        float s = g_s[b * CIN + ci0 + ci];
        tile[ci][j] = x[((size_t)(b * CIN + ci0 + ci)) * PIX + p0 + j] * s;
    }
    __syncthreads();
    #pragma unroll
    for (int ii = 0; ii < 16; ii++) {
        int pl = i0 + ii * 4;
        g_xh[((size_t)b * PIX + p0 + pl) * CIN + ci0 + j] = __float2half_rn(tile[j][pl]);
    }
}

// ---------------- main HMMA implicit-GEMM conv ----------------
// 128x256 CTA, 64x64 warp, k64 chunks; fp16-accumulate over k32, fp32 master acc
__global__ __launch_bounds__(256, 1) void conv_kernel(float* __restrict__ out) {
    extern __shared__ char smem[];
    const uint32_t sb = smem_u32(smem);
    const int tid = threadIdx.x;
    const int ptile = blockIdx.x;            // 16 pixel tiles (256 px = 4 rows)
    const int cout0 = blockIdx.y * 128;      // 4 cout tiles
    const int b = blockIdx.z;
    const int warp = tid >> 5, lane = tid & 31;
    const int mw = warp & 1;                 // 2 m-warps (64 couts each)
    const int nw = warp >> 1;                // 4 n-warps (64 pixels each)

    // staging: every thread stages B row tid; threads 0-127 also stage A row tid
    const bool isA = tid < 128;
    const int py0 = (ptile * 256 + tid) >> 6;
    const int px0 = tid & 63;

    float acc[4][8][4];
    #pragma unroll
    for (int mt = 0; mt < 4; mt++)
        #pragma unroll
        for (int nt = 0; nt < 8; nt++)
            #pragma unroll
            for (int r = 0; r < 4; r++) acc[mt][nt][r] = 0.f;

    #define FETCH(i) do {                                                        \
        int _tap = (i) >> 3;                                                     \
        int _kc  = ((i) & 7) << 6;                                               \
        uint32_t _stb = sb + ((i) % NSTG) * SSTAGE;                              \
        if (isA) {                                                               \
            const __half* _as = g_wh + ((size_t)(cout0 + tid) * 9 + _tap) * CIN + _kc; \
            uint32_t _ad = _stb + A_O + tid * ROWB;                              \
            _Pragma("unroll")                                                    \
            for (int _s = 0; _s < 8; _s++)                                       \
                cpa16(_ad + _s * 16, _as + _s * 8, 16);                          \
        }                                                                        \
        {                                                                        \
            int _dy = _tap / 3, _dx = _tap - _dy * 3;                            \
            int _py = py0 + _dy - 1, _px = px0 + _dx - 1;                        \
            bool _ok = ((unsigned)_py < HH) && ((unsigned)_px < WW);             \
            size_t _xo = _ok ? (((size_t)(b * PIX + _py * WW + _px)) * CIN + _kc) : 0; \
            int _sz = _ok ? 16 : 0;                                              \
            const __half* _bs = g_xh + _xo;                                      \
            uint32_t _bd = _stb + B_O + tid * ROWB;                              \
            _Pragma("unroll")                                                    \
            for (int _s = 0; _s < 8; _s++)                                       \
                cpa16(_bd + _s * 16, _bs + _s * 8, _sz);                         \
        }                                                                        \
        CP_COMMIT();                                                             \
    } while (0)

    FETCH(0);
    FETCH(1);
    FETCH(2);

    // per-lane ldmatrix address components (proven layout)
    const int am = mw * 64 + (lane & 7) + ((lane >> 3) & 1) * 8;   // + mt*16
    const uint32_t akb = ((lane >> 4) & 1) * 16;                   // + kk*32
    const int bn = nw * 64 + ((lane >> 4) & 1) * 8 + (lane & 7);   // + pr*16
    const uint32_t bkb = ((lane >> 3) & 1) * 16;                   // + kk*32

    for (int i = 0; i < NCH; i++) {
        if (i <= NCH - 3)      CP_WAIT2();
        else if (i == NCH - 2) CP_WAIT1();
        else                   CP_WAIT0();
        __syncthreads();
        if (i + 3 < NCH) FETCH(i + 3);

        const uint32_t stb = sb + (i % NSTG) * SSTAGE;
        #pragma unroll
        for (int kg = 0; kg < 2; kg++) {       // two k32 groups per chunk
            // B fragments for both k16 halves of this k32 group
            uint32_t bfr[2][4][4];
            #pragma unroll
            for (int kk = 0; kk < 2; kk++)
                #pragma unroll
                for (int pr = 0; pr < 4; pr++)
                    LDSM4(bfr[kk][pr], stb + B_O + (uint32_t)(bn + pr * 16) * ROWB
                                           + (kg * 2 + kk) * 32 + bkb);
            #pragma unroll
            for (int mt = 0; mt < 4; mt++) {
                uint32_t a0[4], a1[4];
                LDSM4(a0, stb + A_O + (uint32_t)(am + mt * 16) * ROWB + (kg * 2 + 0) * 32 + akb);
                LDSM4(a1, stb + A_O + (uint32_t)(am + mt * 16) * ROWB + (kg * 2 + 1) * 32 + akb);
                #pragma unroll
                for (int nt = 0; nt < 8; nt++) {
                    const int pr = nt >> 1, o = (nt & 1) * 2;
                    uint32_t d0, d1, e0, e1;
                    MMA16816H(d0, d1, a0, bfr[0][pr][o], bfr[0][pr][o + 1], 0u, 0u);
                    MMA16816H(e0, e1, a1, bfr[1][pr][o], bfr[1][pr][o + 1], d0, d1);
                    const float2 f0 = __half22float2(*reinterpret_cast<__half2*>(&e0));
                    const float2 f1 = __half22float2(*reinterpret_cast<__half2*>(&e1));
                    acc[mt][nt][0] += f0.x;
                    acc[mt][nt][1] += f0.y;
                    acc[mt][nt][2] += f1.x;
                    acc[mt][nt][3] += f1.y;
                }
            }
        }
    }

    // ---- epilogue: scale by demod*CONV_SCALE, write float2 ----
    const int r4 = lane >> 2, t4 = lane & 3;
    #pragma unroll
    for (int mt = 0; mt < 4; mt++) {
        const int c0 = cout0 + mw * 64 + mt * 16 + r4;
        const float d0 = g_demod[b * COUT + c0] * CONV_SCALE_F;
        const float d1 = g_demod[b * COUT + c0 + 8] * CONV_SCALE_F;
        #pragma unroll
        for (int nt = 0; nt < 8; nt++) {
            const int pix = ptile * 256 + nw * 64 + nt * 8 + t4 * 2;
            float* p0 = out + ((size_t)(b * COUT + c0)) * PIX + pix;
            float* p1 = out + ((size_t)(b * COUT + c0 + 8)) * PIX + pix;
            float2 v0, v1;
            v0.x = acc[mt][nt][0] * d0; v0.y = acc[mt][nt][1] * d0;
            v1.x = acc[mt][nt][2] * d1; v1.y = acc[mt][nt][3] * d1;
            *(float2*)p0 = v0;
            *(float2*)p1 = v1;
        }
    }
}

// ---------------- launch ----------------
extern "C" void kernel_launch(void* const* d_in, const int* in_sizes, int n_in,
                              void* d_out, int out_size) {
    const float* input  = (const float*)d_in[0];  // [16,512,64,64]
    const float* style  = (const float*)d_in[1];  // [16,512]
    const float* conv_w = (const float*)d_in[2];  // [1,512,512,3,3]
    const float* mod_w  = (const float*)d_in[3];  // [512,512]
    const float* mod_b  = (const float*)d_in[4];  // [512]
    float* out = (float*)d_out;                   // [16,512,64,64]

    modulate_kernel<<<1024, 256>>>(style, mod_w, mod_b);
    wprep_kernel<<<(COUT * CIN + 255) / 256, 256>>>(conv_w);
    demod_kernel<<<1024, 256>>>();
    xprep_kernel<<<dim3(PIX / 64, CIN / 64, B_), 256>>>(input);

    cudaFuncSetAttribute(conv_kernel, cudaFuncAttributeMaxDynamicSharedMemorySize, DSMEM);
    conv_kernel<<<dim3(16, 4, B_), 256, DSMEM>>>(out);
}

// round 13
// speedup vs baseline: 2.0003x; 2.0003x over previous
#include <cuda_runtime.h>
#include <cuda_fp16.h>
#include <cstdint>
#include <math.h>

// ---------------- problem constants ----------------
#define B_    16
#define CIN   512
#define COUT  512
#define HH    64
#define WW    64
#define PIX   4096
#define SD    512
#define NTG   16384              // global Winograd tiles = B_ * 32 * 32
#define EPSV  1e-8f
#define MOD_SCALE_F  0.04419417382415922f   // 1/sqrt(512)
#define CONV_SCALE_F 0.014731391274719738f  // 1/sqrt(512*9)
#define CS2_F        0.00021701388888888888f

// ---------------- GEMM tiling (proven R10 engine) ----------------
// CTA: M=128 couts x N=256 tiles, K-chunk=64 cins, 8 chunks (K=512)
#define NCH   8
#define ROWB  144                // padded smem row bytes (128B data + 16B pad)
#define A_O   0
#define B_O   18432              // A: 128 rows * 144B
#define SSTAGE 55296             // A 18432 | B 36864 (256 rows * 144B)
#define NSTG  4
#define DSMEM (NSTG * SSTAGE)    // 221184 B

// ---------------- scratch ----------------
__device__ float g_s[B_ * CIN];
__device__ float g_wsq[COUT * CIN];
__device__ float g_demod[B_ * COUT];
__device__ float  g_xs[(size_t)B_ * PIX * CIN];          // scaled input, channel-last fp32
__device__ __half g_u[(size_t)16 * COUT * CIN];          // transformed weights [pos][cout][cin]
__device__ __half g_v[(size_t)16 * NTG * CIN];           // transformed input  [pos][tile][cin]
__device__ __half g_m[(size_t)16 * COUT * NTG];          // GEMM result       [pos][cout][tile]

// ---------------- PTX helpers (baseline PTX, sm_80-class) ----------------
__device__ __forceinline__ uint32_t smem_u32(const void* p) {
    uint32_t a;
    asm("{ .reg .u64 t; cvta.to.shared.u64 t, %1; cvt.u32.u64 %0, t; }" : "=r"(a) : "l"(p));
    return a;
}
__device__ __forceinline__ void cpa16(uint32_t dst, const void* src, int srcsize) {
    asm volatile("cp.async.cg.shared.global [%0], [%1], 16, %2;\n"
                 :: "r"(dst), "l"(src), "r"(srcsize) : "memory");
}
#define CP_COMMIT() asm volatile("cp.async.commit_group;" ::: "memory")
#define CP_WAIT2()  asm volatile("cp.async.wait_group 2;" ::: "memory")
#define CP_WAIT1()  asm volatile("cp.async.wait_group 1;" ::: "memory")
#define CP_WAIT0()  asm volatile("cp.async.wait_group 0;" ::: "memory")

#define LDSM4(r, addr) \
    asm volatile("ldmatrix.sync.aligned.m8n8.x4.shared.b16 {%0,%1,%2,%3}, [%4];" \
        : "=r"((r)[0]), "=r"((r)[1]), "=r"((r)[2]), "=r"((r)[3]) : "r"(addr))

#define MMA16816(acc, a, b0, b1) \
    asm volatile("mma.sync.aligned.m16n8k16.row.col.f32.f16.f16.f32 " \
        "{%0,%1,%2,%3},{%4,%5,%6,%7},{%8,%9},{%0,%1,%2,%3};" \
        : "+f"((acc)[0]), "+f"((acc)[1]), "+f"((acc)[2]), "+f"((acc)[3]) \
        : "r"((a)[0]), "r"((a)[1]), "r"((a)[2]), "r"((a)[3]), "r"(b0), "r"(b1))

// ---------------- preprocessing kernels ----------------
__global__ void modulate_kernel(const float* __restrict__ style,
                                const float* __restrict__ mw,
                                const float* __restrict__ mb) {
    int warp = (blockIdx.x * blockDim.x + threadIdx.x) >> 5;
    int lane = threadIdx.x & 31;
    if (warp >= B_ * CIN) return;
    int b = warp / CIN, cin = warp % CIN;
    const float* srow = style + (size_t)b * SD;
    const float* wrow = mw + (size_t)cin * SD;
    float sum = 0.f;
    #pragma unroll 4
    for (int j = lane; j < SD; j += 32) sum += srow[j] * wrow[j];
    #pragma unroll
    for (int o = 16; o; o >>= 1) sum += __shfl_xor_sync(0xffffffffu, sum, o);
    if (lane == 0) g_s[warp] = sum * MOD_SCALE_F + mb[cin];
}

// Winograd weight transform U = G g G^T per (cout,cin), fused wsq
__global__ void wtrans_kernel(const float* __restrict__ cw) {
    int idx = blockIdx.x * blockDim.x + threadIdx.x;
    if (idx >= COUT * CIN) return;
    int cout = idx / CIN;
    int ci = idx - cout * CIN;
    const float* p = cw + (size_t)idx * 9;
    float g[3][3];
    float sq = 0.f;
    #pragma unroll
    for (int k = 0; k < 9; k++) {
        float v = p[k];
        sq += v * v;
        g[k / 3][k % 3] = v;
    }
    g_wsq[idx] = sq;
    float t[4][3];
    #pragma unroll
    for (int c = 0; c < 3; c++) {
        t[0][c] = g[0][c];
        t[1][c] = 0.5f * (g[0][c] + g[1][c] + g[2][c]);
        t[2][c] = 0.5f * (g[0][c] - g[1][c] + g[2][c]);
        t[3][c] = g[2][c];
    }
    #pragma unroll
    for (int r = 0; r < 4; r++) {
        float u0 = t[r][0];
        float u1 = 0.5f * (t[r][0] + t[r][1] + t[r][2]);
        float u2 = 0.5f * (t[r][0] - t[r][1] + t[r][2]);
        float u3 = t[r][2];
        g_u[((size_t)(r * 4 + 0) * COUT + cout) * CIN + ci] = __float2half_rn(u0);
        g_u[((size_t)(r * 4 + 1) * COUT + cout) * CIN + ci] = __float2half_rn(u1);
        g_u[((size_t)(r * 4 + 2) * COUT + cout) * CIN + ci] = __float2half_rn(u2);
        g_u[((size_t)(r * 4 + 3) * COUT + cout) * CIN + ci] = __float2half_rn(u3);
    }
}

__global__ void demod_kernel() {
    int warp = (blockIdx.x * blockDim.x + threadIdx.x) >> 5;
    int lane = threadIdx.x & 31;
    if (warp >= B_ * COUT) return;
    int b = warp / COUT, cout = warp % COUT;
    const float* srow = g_s + (size_t)b * CIN;
    const float* wrow = g_wsq + (size_t)cout * CIN;
    float sum = 0.f;
    #pragma unroll 4
    for (int cin = lane; cin < CIN; cin += 32) {
        float s = srow[cin];
        sum += s * s * wrow[cin];
    }
    #pragma unroll
    for (int o = 16; o; o >>= 1) sum += __shfl_xor_sync(0xffffffffu, sum, o);
    if (lane == 0) g_demod[warp] = rsqrtf(sum * CS2_F + EPSV);
}

// input: [b][ci][p] * s[b][ci] -> channel-last fp32 [b][p][ci]
__global__ __launch_bounds__(256) void xprep_kernel(const float* __restrict__ x) {
    __shared__ float tile[64][65];
    int b = blockIdx.z, ci0 = blockIdx.y * 64, p0 = blockIdx.x * 64;
    int tid = threadIdx.x;
    int j = tid & 63, i0 = tid >> 6;
    #pragma unroll
    for (int ii = 0; ii < 16; ii++) {
        int ci = i0 + ii * 4;
        float s = g_s[b * CIN + ci0 + ci];
        tile[ci][j] = x[((size_t)(b * CIN + ci0 + ci)) * PIX + p0 + j] * s;
    }
    __syncthreads();
    #pragma unroll
    for (int ii = 0; ii < 16; ii++) {
        int pl = i0 + ii * 4;
        g_xs[((size_t)b * PIX + p0 + pl) * CIN + ci0 + j] = tile[j][pl];
    }
}

// Winograd input transform V = B^T d B per (tile, cin)
__global__ __launch_bounds__(256) void xtrans_kernel() {
    int t = blockIdx.x * 256 + threadIdx.x;   // NTG*CIN threads
    int cin = t & (CIN - 1);
    int gtile = t >> 9;
    int b = gtile >> 10;
    int local = gtile & 1023;
    int ty = local >> 5, tx = local & 31;

    float d[4][4];
    #pragma unroll
    for (int r = 0; r < 4; r++) {
        int py = 2 * ty - 1 + r;
        #pragma unroll
        for (int c = 0; c < 4; c++) {
            int px = 2 * tx - 1 + c;
            bool ok = ((unsigned)py < HH) && ((unsigned)px < WW);
            d[r][c] = ok ? g_xs[((size_t)b * PIX + py * WW + px) * CIN + cin] : 0.f;
        }
    }
    float tt[4][4];
    #pragma unroll
    for (int c = 0; c < 4; c++) {
        tt[0][c] = d[0][c] - d[2][c];
        tt[1][c] = d[1][c] + d[2][c];
        tt[2][c] = d[2][c] - d[1][c];
        tt[3][c] = d[1][c] - d[3][c];
    }
    #pragma unroll
    for (int r = 0; r < 4; r++) {
        float v0 = tt[r][0] - tt[r][2];
        float v1 = tt[r][1] + tt[r][2];
        float v2 = tt[r][2] - tt[r][1];
        float v3 = tt[r][1] - tt[r][3];
        g_v[((size_t)(r * 4 + 0) * NTG + gtile) * CIN + cin] = __float2half_rn(v0);
        g_v[((size_t)(r * 4 + 1) * NTG + gtile) * CIN + cin] = __float2half_rn(v1);
        g_v[((size_t)(r * 4 + 2) * NTG + gtile) * CIN + cin] = __float2half_rn(v2);
        g_v[((size_t)(r * 4 + 3) * NTG + gtile) * CIN + cin] = __float2half_rn(v3);
    }
}

// ---------------- batched Winograd GEMM ----------------
// M[pos][cout][tile] = sum_cin U[pos][cout][cin] * V[pos][tile][cin]
__global__ __launch_bounds__(256, 1) void gemm_kernel() {
    extern __shared__ char smem[];
    const uint32_t sb = smem_u32(smem);
    const int tid = threadIdx.x;
    const int tile0 = blockIdx.x * 256;      // 64 tile-blocks
    const int cout0 = blockIdx.y * 128;      // 4 cout tiles
    const int pos = blockIdx.z;              // 16 Winograd positions
    const int warp = tid >> 5, lane = tid & 31;
    const int mw = warp & 1;
    const int nw = warp >> 1;
    const bool isA = tid < 128;

    float acc[4][8][4];
    #pragma unroll
    for (int mt = 0; mt < 4; mt++)
        #pragma unroll
        for (int nt = 0; nt < 8; nt++)
            #pragma unroll
            for (int r = 0; r < 4; r++) acc[mt][nt][r] = 0.f;

    #define FETCH(i) do {                                                        \
        int _kc = (i) << 6;                                                      \
        uint32_t _stb = sb + ((i) % NSTG) * SSTAGE;                              \
        if (isA) {                                                               \
            const __half* _as = g_u + ((size_t)pos * COUT + cout0 + tid) * CIN + _kc; \
            uint32_t _ad = _stb + A_O + tid * ROWB;                              \
            _Pragma("unroll")                                                    \
            for (int _s = 0; _s < 8; _s++)                                       \
                cpa16(_ad + _s * 16, _as + _s * 8, 16);                          \
        }                                                                        \
        {                                                                        \
            const __half* _bs = g_v + ((size_t)pos * NTG + tile0 + tid) * CIN + _kc; \
            uint32_t _bd = _stb + B_O + tid * ROWB;                              \
            _Pragma("unroll")                                                    \
            for (int _s = 0; _s < 8; _s++)                                       \
                cpa16(_bd + _s * 16, _bs + _s * 8, 16);                          \
        }                                                                        \
        CP_COMMIT();                                                             \
    } while (0)

    FETCH(0);
    FETCH(1);
    FETCH(2);

    const int am = mw * 64 + (lane & 7) + ((lane >> 3) & 1) * 8;   // + mt*16
    const uint32_t akb = ((lane >> 4) & 1) * 16;                   // + kk*32
    const int bn = nw * 64 + ((lane >> 4) & 1) * 8 + (lane & 7);   // + pr*16
    const uint32_t bkb = ((lane >> 3) & 1) * 16;                   // + kk*32

    for (int i = 0; i < NCH; i++) {
        if (i <= NCH - 3)      CP_WAIT2();
        else if (i == NCH - 2) CP_WAIT1();
        else                   CP_WAIT0();
        __syncthreads();
        if (i + 3 < NCH) FETCH(i + 3);

        const uint32_t stb = sb + (i % NSTG) * SSTAGE;
        #pragma unroll
        for (int kk = 0; kk < 4; kk++) {
            uint32_t a[4][4], bfr[4][4];
            #pragma unroll
            for (int mt = 0; mt < 4; mt++)
                LDSM4(a[mt], stb + A_O + (uint32_t)(am + mt * 16) * ROWB + kk * 32 + akb);
            #pragma unroll
            for (int pr = 0; pr < 4; pr++)
                LDSM4(bfr[pr], stb + B_O + (uint32_t)(bn + pr * 16) * ROWB + kk * 32 + bkb);
            #pragma unroll
            for (int mt = 0; mt < 4; mt++)
                #pragma unroll
                for (int nt = 0; nt < 8; nt++) {
                    const int pr = nt >> 1, o = (nt & 1) * 2;
                    MMA16816(acc[mt][nt], a[mt], bfr[pr][o], bfr[pr][o + 1]);
                }
        }
    }

    // epilogue: write M as fp16 [pos][cout][tile]
    const int r4 = lane >> 2, t4 = lane & 3;
    #pragma unroll
    for (int mt = 0; mt < 4; mt++) {
        const int c0 = cout0 + mw * 64 + mt * 16 + r4;
        #pragma unroll
        for (int nt = 0; nt < 8; nt++) {
            const int pix = tile0 + nw * 64 + nt * 8 + t4 * 2;
            __half2 h0 = __floats2half2_rn(acc[mt][nt][0], acc[mt][nt][1]);
            __half2 h1 = __floats2half2_rn(acc[mt][nt][2], acc[mt][nt][3]);
            *(__half2*)&g_m[((size_t)pos * COUT + c0) * NTG + pix] = h0;
            *(__half2*)&g_m[((size_t)pos * COUT + c0 + 8) * NTG + pix] = h1;
        }
    }
}

// ---------------- Winograd output transform ----------------
// Y = A^T M A, scaled by demod*CONV_SCALE
__global__ __launch_bounds__(256) void otrans_kernel(float* __restrict__ out) {
    int t = blockIdx.x * 256 + threadIdx.x;   // COUT*NTG threads
    int gtile = t & (NTG - 1);
    int cout = t >> 14;
    float M[4][4];
    #pragma unroll
    for (int r = 0; r < 4; r++)
        #pragma unroll
        for (int c = 0; c < 4; c++)
            M[r][c] = __half2float(g_m[((size_t)(r * 4 + c) * COUT + cout) * NTG + gtile]);

    float t0[4], t1[4];
    #pragma unroll
    for (int c = 0; c < 4; c++) {
        t0[c] = M[0][c] + M[1][c] + M[2][c];
        t1[c] = M[1][c] - M[2][c] - M[3][c];
    }
    float y00 = t0[0] + t0[1] + t0[2];
    float y01 = t0[1] - t0[2] - t0[3];
    float y10 = t1[0] + t1[1] + t1[2];
    float y11 = t1[1] - t1[2] - t1[3];

    int b = gtile >> 10;
    int local = gtile & 1023;
    int ty = local >> 5, tx = local & 31;
    float d = g_demod[b * COUT + cout] * CONV_SCALE_F;

    float* o0 = out + (((size_t)(b * COUT + cout)) * HH + 2 * ty) * WW + 2 * tx;
    float2 v0; v0.x = y00 * d; v0.y = y01 * d;
    float2 v1; v1.x = y10 * d; v1.y = y11 * d;
    *(float2*)o0 = v0;
    *(float2*)(o0 + WW) = v1;
}

// ---------------- launch ----------------
extern "C" void kernel_launch(void* const* d_in, const int* in_sizes, int n_in,
                              void* d_out, int out_size) {
    const float* input  = (const float*)d_in[0];  // [16,512,64,64]
    const float* style  = (const float*)d_in[1];  // [16,512]
    const float* conv_w = (const float*)d_in[2];  // [1,512,512,3,3]
    const float* mod_w  = (const float*)d_in[3];  // [512,512]
    const float* mod_b  = (const float*)d_in[4];  // [512]
    float* out = (float*)d_out;                   // [16,512,64,64]

    modulate_kernel<<<1024, 256>>>(style, mod_w, mod_b);
    wtrans_kernel<<<(COUT * CIN + 255) / 256, 256>>>(conv_w);
    demod_kernel<<<1024, 256>>>();
    xprep_kernel<<<dim3(PIX / 64, CIN / 64, B_), 256>>>(input);
    xtrans_kernel<<<(NTG * CIN) / 256, 256>>>();

    cudaFuncSetAttribute(gemm_kernel, cudaFuncAttributeMaxDynamicSharedMemorySize, DSMEM);
    gemm_kernel<<<dim3(NTG / 256, COUT / 128, 16), 256, DSMEM>>>();

    otrans_kernel<<<(COUT * NTG) / 256, 256>>>(out);
}

// round 14
// speedup vs baseline: 2.1170x; 1.0583x over previous
#include <cuda_runtime.h>
#include <cuda_fp16.h>
#include <cstdint>
#include <math.h>

// ---------------- problem constants ----------------
#define B_    16
#define CIN   512
#define COUT  512
#define HH    64
#define WW    64
#define PIX   4096
#define SD    512
#define NTG   16384              // global Winograd tiles = B_ * 32 * 32
#define EPSV  1e-8f
#define MOD_SCALE_F  0.04419417382415922f   // 1/sqrt(512)
#define CONV_SCALE_F 0.014731391274719738f  // 1/sqrt(512*9)
#define CS2_F        0.00021701388888888888f

// ---------------- GEMM tiling (proven R10/R13 engine) ----------------
#define NCH   8
#define ROWB  144                // padded smem row bytes (128B data + 16B pad)
#define A_O   0
#define B_O   18432              // A: 128 rows * 144B
#define SSTAGE 55296             // A 18432 | B 36864 (256 rows * 144B)
#define NSTG  4
#define DSMEM (NSTG * SSTAGE)    // 221184 B

// ---------------- scratch ----------------
__device__ float g_s[B_ * CIN];
__device__ float g_wsq[COUT * CIN];
__device__ float g_demod[B_ * COUT];
__device__ __half g_xs[(size_t)B_ * PIX * CIN];          // scaled input, channel-last fp16
__device__ __half g_u[(size_t)16 * COUT * CIN];          // transformed weights [pos][cout][cin]
__device__ __half g_v[(size_t)16 * NTG * CIN];           // transformed input  [pos][tile][cin]
__device__ __half g_m[(size_t)16 * COUT * NTG];          // GEMM result       [pos][cout][tile]

// ---------------- PTX helpers (baseline PTX, sm_80-class) ----------------
__device__ __forceinline__ uint32_t smem_u32(const void* p) {
    uint32_t a;
    asm("{ .reg .u64 t; cvta.to.shared.u64 t, %1; cvt.u32.u64 %0, t; }" : "=r"(a) : "l"(p));
    return a;
}
__device__ __forceinline__ void cpa16(uint32_t dst, const void* src, int srcsize) {
    asm volatile("cp.async.cg.shared.global [%0], [%1], 16, %2;\n"
                 :: "r"(dst), "l"(src), "r"(srcsize) : "memory");
}
#define CP_COMMIT() asm volatile("cp.async.commit_group;" ::: "memory")
#define CP_WAIT2()  asm volatile("cp.async.wait_group 2;" ::: "memory")
#define CP_WAIT1()  asm volatile("cp.async.wait_group 1;" ::: "memory")
#define CP_WAIT0()  asm volatile("cp.async.wait_group 0;" ::: "memory")

#define LDSM4(r, addr) \
    asm volatile("ldmatrix.sync.aligned.m8n8.x4.shared.b16 {%0,%1,%2,%3}, [%4];" \
        : "=r"((r)[0]), "=r"((r)[1]), "=r"((r)[2]), "=r"((r)[3]) : "r"(addr))

#define MMA16816(acc, a, b0, b1) \
    asm volatile("mma.sync.aligned.m16n8k16.row.col.f32.f16.f16.f32 " \
        "{%0,%1,%2,%3},{%4,%5,%6,%7},{%8,%9},{%0,%1,%2,%3};" \
        : "+f"((acc)[0]), "+f"((acc)[1]), "+f"((acc)[2]), "+f"((acc)[3]) \
        : "r"((a)[0]), "r"((a)[1]), "r"((a)[2]), "r"((a)[3]), "r"(b0), "r"(b1))

// float2 elementwise helpers
__device__ __forceinline__ float2 f2add(float2 a, float2 b) { return make_float2(a.x + b.x, a.y + b.y); }
__device__ __forceinline__ float2 f2sub(float2 a, float2 b) { return make_float2(a.x - b.x, a.y - b.y); }

// ---------------- preprocessing kernels ----------------
__global__ void modulate_kernel(const float* __restrict__ style,
                                const float* __restrict__ mw,
                                const float* __restrict__ mb) {
    int warp = (blockIdx.x * blockDim.x + threadIdx.x) >> 5;
    int lane = threadIdx.x & 31;
    if (warp >= B_ * CIN) return;
    int b = warp / CIN, cin = warp % CIN;
    const float* srow = style + (size_t)b * SD;
    const float* wrow = mw + (size_t)cin * SD;
    float sum = 0.f;
    #pragma unroll 4
    for (int j = lane; j < SD; j += 32) sum += srow[j] * wrow[j];
    #pragma unroll
    for (int o = 16; o; o >>= 1) sum += __shfl_xor_sync(0xffffffffu, sum, o);
    if (lane == 0) g_s[warp] = sum * MOD_SCALE_F + mb[cin];
}

// Winograd weight transform U = G g G^T per (cout,cin), fused wsq
__global__ void wtrans_kernel(const float* __restrict__ cw) {
    int idx = blockIdx.x * blockDim.x + threadIdx.x;
    if (idx >= COUT * CIN) return;
    int cout = idx / CIN;
    int ci = idx - cout * CIN;
    const float* p = cw + (size_t)idx * 9;
    float g[3][3];
    float sq = 0.f;
    #pragma unroll
    for (int k = 0; k < 9; k++) {
        float v = p[k];
        sq += v * v;
        g[k / 3][k % 3] = v;
    }
    g_wsq[idx] = sq;
    float t[4][3];
    #pragma unroll
    for (int c = 0; c < 3; c++) {
        t[0][c] = g[0][c];
        t[1][c] = 0.5f * (g[0][c] + g[1][c] + g[2][c]);
        t[2][c] = 0.5f * (g[0][c] - g[1][c] + g[2][c]);
        t[3][c] = g[2][c];
    }
    #pragma unroll
    for (int r = 0; r < 4; r++) {
        float u0 = t[r][0];
        float u1 = 0.5f * (t[r][0] + t[r][1] + t[r][2]);
        float u2 = 0.5f * (t[r][0] - t[r][1] + t[r][2]);
        float u3 = t[r][2];
        g_u[((size_t)(r * 4 + 0) * COUT + cout) * CIN + ci] = __float2half_rn(u0);
        g_u[((size_t)(r * 4 + 1) * COUT + cout) * CIN + ci] = __float2half_rn(u1);
        g_u[((size_t)(r * 4 + 2) * COUT + cout) * CIN + ci] = __float2half_rn(u2);
        g_u[((size_t)(r * 4 + 3) * COUT + cout) * CIN + ci] = __float2half_rn(u3);
    }
}

__global__ void demod_kernel() {
    int warp = (blockIdx.x * blockDim.x + threadIdx.x) >> 5;
    int lane = threadIdx.x & 31;
    if (warp >= B_ * COUT) return;
    int b = warp / COUT, cout = warp % COUT;
    const float* srow = g_s + (size_t)b * CIN;
    const float* wrow = g_wsq + (size_t)cout * CIN;
    float sum = 0.f;
    #pragma unroll 4
    for (int cin = lane; cin < CIN; cin += 32) {
        float s = srow[cin];
        sum += s * s * wrow[cin];
    }
    #pragma unroll
    for (int o = 16; o; o >>= 1) sum += __shfl_xor_sync(0xffffffffu, sum, o);
    if (lane == 0) g_demod[warp] = rsqrtf(sum * CS2_F + EPSV);
}

// input: [b][ci][p] * s[b][ci] -> channel-last fp16 [b][p][ci]
__global__ __launch_bounds__(256) void xprep_kernel(const float* __restrict__ x) {
    __shared__ float tile[64][65];
    int b = blockIdx.z, ci0 = blockIdx.y * 64, p0 = blockIdx.x * 64;
    int tid = threadIdx.x;
    int j = tid & 63, i0 = tid >> 6;
    #pragma unroll
    for (int ii = 0; ii < 16; ii++) {
        int ci = i0 + ii * 4;
        float s = g_s[b * CIN + ci0 + ci];
        tile[ci][j] = x[((size_t)(b * CIN + ci0 + ci)) * PIX + p0 + j] * s;
    }
    __syncthreads();
    #pragma unroll
    for (int ii = 0; ii < 16; ii++) {
        int pl = i0 + ii * 4;
        g_xs[((size_t)b * PIX + p0 + pl) * CIN + ci0 + j] = __float2half_rn(tile[j][pl]);
    }
}

// Winograd input transform V = B^T d B per (tile, cin-pair), half2-vectorized
__global__ __launch_bounds__(256) void xtrans_kernel() {
    int t = blockIdx.x * 256 + threadIdx.x;   // NTG * CIN/2 threads
    int cp = t & (CIN / 2 - 1);
    int gtile = t >> 8;
    int cin = cp * 2;
    int b = gtile >> 10;
    int local = gtile & 1023;
    int ty = local >> 5, tx = local & 31;

    float2 d[4][4];
    #pragma unroll
    for (int r = 0; r < 4; r++) {
        int py = 2 * ty - 1 + r;
        #pragma unroll
        for (int c = 0; c < 4; c++) {
            int px = 2 * tx - 1 + c;
            bool ok = ((unsigned)py < HH) && ((unsigned)px < WW);
            d[r][c] = ok
                ? __half22float2(*(const __half2*)&g_xs[((size_t)b * PIX + py * WW + px) * CIN + cin])
                : make_float2(0.f, 0.f);
        }
    }
    float2 tt[4][4];
    #pragma unroll
    for (int c = 0; c < 4; c++) {
        tt[0][c] = f2sub(d[0][c], d[2][c]);
        tt[1][c] = f2add(d[1][c], d[2][c]);
        tt[2][c] = f2sub(d[2][c], d[1][c]);
        tt[3][c] = f2sub(d[1][c], d[3][c]);
    }
    #pragma unroll
    for (int r = 0; r < 4; r++) {
        float2 v0 = f2sub(tt[r][0], tt[r][2]);
        float2 v1 = f2add(tt[r][1], tt[r][2]);
        float2 v2 = f2sub(tt[r][2], tt[r][1]);
        float2 v3 = f2sub(tt[r][1], tt[r][3]);
        *(__half2*)&g_v[((size_t)(r * 4 + 0) * NTG + gtile) * CIN + cin] = __float22half2_rn(v0);
        *(__half2*)&g_v[((size_t)(r * 4 + 1) * NTG + gtile) * CIN + cin] = __float22half2_rn(v1);
        *(__half2*)&g_v[((size_t)(r * 4 + 2) * NTG + gtile) * CIN + cin] = __float22half2_rn(v2);
        *(__half2*)&g_v[((size_t)(r * 4 + 3) * NTG + gtile) * CIN + cin] = __float22half2_rn(v3);
    }
}

// ---------------- batched Winograd GEMM (unchanged proven engine) -----------
__global__ __launch_bounds__(256, 1) void gemm_kernel() {
    extern __shared__ char smem[];
    const uint32_t sb = smem_u32(smem);
    const int tid = threadIdx.x;
    const int tile0 = blockIdx.x * 256;
    const int cout0 = blockIdx.y * 128;
    const int pos = blockIdx.z;
    const int warp = tid >> 5, lane = tid & 31;
    const int mw = warp & 1;
    const int nw = warp >> 1;
    const bool isA = tid < 128;

    float acc[4][8][4];
    #pragma unroll
    for (int mt = 0; mt < 4; mt++)
        #pragma unroll
        for (int nt = 0; nt < 8; nt++)
            #pragma unroll
            for (int r = 0; r < 4; r++) acc[mt][nt][r] = 0.f;

    #define FETCH(i) do {                                                        \
        int _kc = (i) << 6;                                                      \
        uint32_t _stb = sb + ((i) % NSTG) * SSTAGE;                              \
        if (isA) {                                                               \
            const __half* _as = g_u + ((size_t)pos * COUT + cout0 + tid) * CIN + _kc; \
            uint32_t _ad = _stb + A_O + tid * ROWB;                              \
            _Pragma("unroll")                                                    \
            for (int _s = 0; _s < 8; _s++)                                       \
                cpa16(_ad + _s * 16, _as + _s * 8, 16);                          \
        }                                                                        \
        {                                                                        \
            const __half* _bs = g_v + ((size_t)pos * NTG + tile0 + tid) * CIN + _kc; \
            uint32_t _bd = _stb + B_O + tid * ROWB;                              \
            _Pragma("unroll")                                                    \
            for (int _s = 0; _s < 8; _s++)                                       \
                cpa16(_bd + _s * 16, _bs + _s * 8, 16);                          \
        }                                                                        \
        CP_COMMIT();                                                             \
    } while (0)

    FETCH(0);
    FETCH(1);
    FETCH(2);

    const int am = mw * 64 + (lane & 7) + ((lane >> 3) & 1) * 8;
    const uint32_t akb = ((lane >> 4) & 1) * 16;
    const int bn = nw * 64 + ((lane >> 4) & 1) * 8 + (lane & 7);
    const uint32_t bkb = ((lane >> 3) & 1) * 16;

    for (int i = 0; i < NCH; i++) {
        if (i <= NCH - 3)      CP_WAIT2();
        else if (i == NCH - 2) CP_WAIT1();
        else                   CP_WAIT0();
        __syncthreads();
        if (i + 3 < NCH) FETCH(i + 3);

        const uint32_t stb = sb + (i % NSTG) * SSTAGE;
        #pragma unroll
        for (int kk = 0; kk < 4; kk++) {
            uint32_t a[4][4], bfr[4][4];
            #pragma unroll
            for (int mt = 0; mt < 4; mt++)
                LDSM4(a[mt], stb + A_O + (uint32_t)(am + mt * 16) * ROWB + kk * 32 + akb);
            #pragma unroll
            for (int pr = 0; pr < 4; pr++)
                LDSM4(bfr[pr], stb + B_O + (uint32_t)(bn + pr * 16) * ROWB + kk * 32 + bkb);
            #pragma unroll
            for (int mt = 0; mt < 4; mt++)
                #pragma unroll
                for (int nt = 0; nt < 8; nt++) {
                    const int pr = nt >> 1, o = (nt & 1) * 2;
                    MMA16816(acc[mt][nt], a[mt], bfr[pr][o], bfr[pr][o + 1]);
                }
        }
    }

    const int r4 = lane >> 2, t4 = lane & 3;
    #pragma unroll
    for (int mt = 0; mt < 4; mt++) {
        const int c0 = cout0 + mw * 64 + mt * 16 + r4;
        #pragma unroll
        for (int nt = 0; nt < 8; nt++) {
            const int pix = tile0 + nw * 64 + nt * 8 + t4 * 2;
            __half2 h0 = __floats2half2_rn(acc[mt][nt][0], acc[mt][nt][1]);
            __half2 h1 = __floats2half2_rn(acc[mt][nt][2], acc[mt][nt][3]);
            *(__half2*)&g_m[((size_t)pos * COUT + c0) * NTG + pix] = h0;
            *(__half2*)&g_m[((size_t)pos * COUT + c0 + 8) * NTG + pix] = h1;
        }
    }
}

// ---------------- Winograd output transform (tile-pair vectorized) ----------
// Y = A^T M A, scaled by demod*CONV_SCALE; 2 adjacent tiles per thread
__global__ __launch_bounds__(256) void otrans_kernel(float* __restrict__ out) {
    int t = blockIdx.x * 256 + threadIdx.x;   // COUT*NTG/2 threads
    int pg = t & (NTG / 2 - 1);
    int cout = t >> 13;
    int gtile = pg * 2;

    float2 M[4][4];
    #pragma unroll
    for (int r = 0; r < 4; r++)
        #pragma unroll
        for (int c = 0; c < 4; c++)
            M[r][c] = __half22float2(
                *(const __half2*)&g_m[((size_t)(r * 4 + c) * COUT + cout) * NTG + gtile]);

    float2 t0[4], t1[4];
    #pragma unroll
    for (int c = 0; c < 4; c++) {
        t0[c] = f2add(f2add(M[0][c], M[1][c]), M[2][c]);
        t1[c] = f2sub(f2sub(M[1][c], M[2][c]), M[3][c]);
    }
    float2 y00 = f2add(f2add(t0[0], t0[1]), t0[2]);
    float2 y01 = f2sub(f2sub(t0[1], t0[2]), t0[3]);
    float2 y10 = f2add(f2add(t1[0], t1[1]), t1[2]);
    float2 y11 = f2sub(f2sub(t1[1], t1[2]), t1[3]);

    int b = gtile >> 10;
    int local = gtile & 1023;
    int ty = local >> 5, tx = local & 31;      // tx even
    float d = g_demod[b * COUT + cout] * CONV_SCALE_F;

    float* o0 = out + (((size_t)(b * COUT + cout)) * HH + 2 * ty) * WW + 2 * tx;
    float4 r0, r1;
    r0.x = y00.x * d; r0.y = y01.x * d; r0.z = y00.y * d; r0.w = y01.y * d;
    r1.x = y10.x * d; r1.y = y11.x * d; r1.z = y10.y * d; r1.w = y11.y * d;
    *(float4*)o0 = r0;
    *(float4*)(o0 + WW) = r1;
}

// ---------------- launch ----------------
extern "C" void kernel_launch(void* const* d_in, const int* in_sizes, int n_in,
                              void* d_out, int out_size) {
    const float* input  = (const float*)d_in[0];  // [16,512,64,64]
    const float* style  = (const float*)d_in[1];  // [16,512]
    const float* conv_w = (const float*)d_in[2];  // [1,512,512,3,3]
    const float* mod_w  = (const float*)d_in[3];  // [512,512]
    const float* mod_b  = (const float*)d_in[4];  // [512]
    float* out = (float*)d_out;                   // [16,512,64,64]

    modulate_kernel<<<1024, 256>>>(style, mod_w, mod_b);
    wtrans_kernel<<<(COUT * CIN + 255) / 256, 256>>>(conv_w);
    demod_kernel<<<1024, 256>>>();
    xprep_kernel<<<dim3(PIX / 64, CIN / 64, B_), 256>>>(input);
    xtrans_kernel<<<(NTG * CIN / 2) / 256, 256>>>();

    cudaFuncSetAttribute(gemm_kernel, cudaFuncAttributeMaxDynamicSharedMemorySize, DSMEM);
    gemm_kernel<<<dim3(NTG / 256, COUT / 128, 16), 256, DSMEM>>>();

    otrans_kernel<<<(COUT * NTG / 2) / 256, 256>>>(out);
}